// round 16
// baseline (speedup 1.0000x reference)
#include <cuda_runtime.h>

// HistogramLoss fused single-kernel reduction (decision numerics bit-preserved).
// Reference accepts pixel into bin k iff powf32(1.01, z) > 1.0f with
// z = fl(W - fl(|y - c_k|)); proven == z > Z_C (libdevice crossing, R4/R5).
// 2x-scaled exact reformulation: s = fl(x+1) => y = s/2 exactly;
// fl(s - c2)/2 == fl(y - c) bit-exactly (rounding commutes with *2), so
//   d_ref = |t|/2,  z_ref = fl(W2 - |t|)/2  bit-exactly (Sterbenz near bound).
// Decision: |t| < T2 = 2(W - Z_C).  Value: (64-k)*(1 + ln(1.01)*z) via LUT:
//   contrib = fma(wkc, z2, wk),  wk = 64-k, wkc = (64-k)*ln(1.01)/2.
// Bin select: magic-number floor, &63 wrap (wrong center => reject, safe).
// YUV: XLA unfused emission — separate FMUL/FADD, left-assoc, NO contraction.
// loss = (1/(B*H*W)) * sum_{pixels, 6ch(RGB+YUV)} [w(input) - w(reference)]

#define HW    65536
#define TPB   128
#define NBLK  512          // 65536 threads, 8 pixels each
#define MAGICF 12582912.0f // 1.5 * 2^23: RN(ef' + MAGIC) has integer = round(ef')

__device__ double g_partial[NBLK];
__device__ unsigned int g_ticket = 0;

__device__ __forceinline__ float binw(float x, const float4* __restrict__ tab,
                                      float W2, float T2) {
    float s  = __fadd_rn(x, 1.0f);                  // y = s/2 exactly
    float ef = fmaf(x, 29.090909090909f, 31.5f);    // selector - 0.5
    float m  = __fadd_rn(ef, MAGICF);               // integer(m) = floor(selector)
    int   i  = __float_as_int(m) & 63;              // wrap => reject path
    float4 e = tab[i];                              // {c2, wk, wkc, 0} one LDS.128
    float t  = __fsub_rn(s, e.x);                   // fl(s-c2) = 2*fl(y-c) exact
    float at = fabsf(t);
    float z2 = __fsub_rn(W2, at);                   // = 2*z_ref bit-exact
    float contrib = fmaf(e.z, z2, e.y);             // (64-k)*(1+ln1.01*z)
    return (at < T2) ? contrib : 0.0f;
}

__device__ __forceinline__ float pix6(float r, float g, float b,
                                      const float4* __restrict__ tab,
                                      float W2, float T2) {
    float s = binw(r, tab, W2, T2) + binw(g, tab, W2, T2) + binw(b, tab, W2, T2);
    // Ordering (B): separate mul / add, left-assoc, every op rounded, NO fma.
    float yy = __fadd_rn(__fadd_rn(__fmul_rn(0.299f,    r), __fmul_rn(0.587f,    g)),
                         __fmul_rn(0.114f,    b));
    float uu = __fadd_rn(__fadd_rn(__fmul_rn(-0.14713f, r), __fmul_rn(-0.28886f, g)),
                         __fmul_rn(0.436f,    b));
    float vv = __fadd_rn(__fadd_rn(__fmul_rn(0.615f,    r), __fmul_rn(-0.51499f, g)),
                         __fmul_rn(-0.10001f, b));
    return s + binw(yy, tab, W2, T2) + binw(uu, tab, W2, T2) + binw(vv, tab, W2, T2);
}

__global__ void __launch_bounds__(TPB, 4) hist_all(const float* __restrict__ A,
                                                   const float* __restrict__ R,
                                                   float* __restrict__ out,
                                                   double inv_n) {
    __shared__ float4 tab[64];
    __shared__ float sW2, sT2;
    __shared__ double sd[TPB];
    __shared__ bool amLast;

    // Exact f32 centers mirroring numpy linspace f64 rounding; x2 scaling exact.
    if (threadIdx.x < 64) {
        double start = -0.05;
        double step  = __ddiv_rn(__dsub_rn(1.05, start), 64.0);
        double e1    = __dadd_rn(__dmul_rn(1.0, step), start);
        double e2    = __dadd_rn(__dmul_rn(2.0, step), start);
        double delta = __dsub_rn(e2, e1);
        double half  = __dmul_rn(delta, 0.5);
        double ei    = __dadd_rn(__dmul_rn((double)threadIdx.x, step), start);
        float  c     = (float)__dadd_rn(ei, half);       // reference center f32
        float  wk    = (float)(64 - (int)threadIdx.x);
        float  wkc   = (float)((64.0 - (double)threadIdx.x) * 0.004975165426584801);
        tab[threadIdx.x] = make_float4(2.0f * c, wk, wkc, 0.0f);
        if (threadIdx.x == 0) {
            float W = (float)half;                        // reference W f32
            sW2 = 2.0f * W;                               // exact
            sT2 = (float)(2.0 * ((double)W - 5.990216e-6)); // 2(W - Z_C)
        }
    }
    __syncthreads();
    float W2 = sW2, T2 = sT2;

    // 8 pixels per thread: two float4 groups per channel per image.
    int gid = blockIdx.x * TPB + threadIdx.x;     // 0 .. 65535
    int b   = gid >> 13;                          // / (HW/8)
    int p8  = (gid & 8191) << 3;                  // 8 consecutive pixels
    size_t base = (size_t)b * (3 * HW) + p8;

    float4 ar0 = *(const float4*)(A + base);
    float4 ar1 = *(const float4*)(A + base + 4);
    float4 ag0 = *(const float4*)(A + base + HW);
    float4 ag1 = *(const float4*)(A + base + HW + 4);
    float4 ab0 = *(const float4*)(A + base + 2 * HW);
    float4 ab1 = *(const float4*)(A + base + 2 * HW + 4);
    float4 rr0 = *(const float4*)(R + base);
    float4 rr1 = *(const float4*)(R + base + 4);
    float4 rg0 = *(const float4*)(R + base + HW);
    float4 rg1 = *(const float4*)(R + base + HW + 4);
    float4 rb0 = *(const float4*)(R + base + 2 * HW);
    float4 rb1 = *(const float4*)(R + base + 2 * HW + 4);

    float acc;
    acc  = pix6(ar0.x, ag0.x, ab0.x, tab, W2, T2) - pix6(rr0.x, rg0.x, rb0.x, tab, W2, T2);
    acc += pix6(ar0.y, ag0.y, ab0.y, tab, W2, T2) - pix6(rr0.y, rg0.y, rb0.y, tab, W2, T2);
    acc += pix6(ar0.z, ag0.z, ab0.z, tab, W2, T2) - pix6(rr0.z, rg0.z, rb0.z, tab, W2, T2);
    acc += pix6(ar0.w, ag0.w, ab0.w, tab, W2, T2) - pix6(rr0.w, rg0.w, rb0.w, tab, W2, T2);
    acc += pix6(ar1.x, ag1.x, ab1.x, tab, W2, T2) - pix6(rr1.x, rg1.x, rb1.x, tab, W2, T2);
    acc += pix6(ar1.y, ag1.y, ab1.y, tab, W2, T2) - pix6(rr1.y, rg1.y, rb1.y, tab, W2, T2);
    acc += pix6(ar1.z, ag1.z, ab1.z, tab, W2, T2) - pix6(rr1.z, rg1.z, rb1.z, tab, W2, T2);
    acc += pix6(ar1.w, ag1.w, ab1.w, tab, W2, T2) - pix6(rr1.w, rg1.w, rb1.w, tab, W2, T2);

    sd[threadIdx.x] = (double)acc;
    __syncthreads();
    #pragma unroll
    for (int s = TPB / 2; s > 32; s >>= 1) {
        if (threadIdx.x < s) sd[threadIdx.x] += sd[threadIdx.x + s];
        __syncthreads();
    }
    if (threadIdx.x < 32) {
        double v = sd[threadIdx.x] + sd[threadIdx.x + 32];
        #pragma unroll
        for (int o = 16; o > 0; o >>= 1)
            v += __shfl_down_sync(0xffffffffu, v, o);
        if (threadIdx.x == 0) g_partial[blockIdx.x] = v;
    }

    // Last-block final reduction (deterministic fixed tree over partials).
    if (threadIdx.x == 0) {
        __threadfence();
        unsigned int t = atomicAdd(&g_ticket, 1u);
        amLast = (t == (unsigned int)(gridDim.x - 1));
    }
    __syncthreads();
    if (amLast) {
        __threadfence();
        double v = 0.0;
        #pragma unroll
        for (int i = 0; i < NBLK / TPB; i++)
            v += g_partial[threadIdx.x + i * TPB];
        sd[threadIdx.x] = v;
        __syncthreads();
        #pragma unroll
        for (int s = TPB / 2; s > 32; s >>= 1) {
            if (threadIdx.x < s) sd[threadIdx.x] += sd[threadIdx.x + s];
            __syncthreads();
        }
        if (threadIdx.x < 32) {
            double w2 = sd[threadIdx.x] + sd[threadIdx.x + 32];
            #pragma unroll
            for (int o = 16; o > 0; o >>= 1)
                w2 += __shfl_down_sync(0xffffffffu, w2, o);
            if (threadIdx.x == 0) {
                out[0] = (float)(w2 * inv_n);
                g_ticket = 0;           // reset for next graph replay
            }
        }
    }
}

extern "C" void kernel_launch(void* const* d_in, const int* in_sizes, int n_in,
                              void* d_out, int out_size) {
    const float* A = (const float*)d_in[0];   // input_img
    const float* R = (const float*)d_in[1];   // reference_img
    int total = in_sizes[0];                  // B*3*HW
    int npix  = total / 3;                    // B*HW
    hist_all<<<NBLK, TPB>>>(A, R, (float*)d_out, 1.0 / (double)npix);
}

// round 17
// speedup vs baseline: 1.3409x; 1.3409x over previous
#include <cuda_runtime.h>

// HistogramLoss fused single-kernel reduction (decision numerics bit-proven:
// R16 produced rel_err identical to R14 => 2x-domain decision |t| < T2 and the
// linearized value path are exact w.r.t. the locked reference semantics).
// 2x-scaled: s = fl(x+1) = 2y exactly; t = fl(s - 2c) = 2*fl(y-c) bit-exact;
// accept iff |t| < T2 = f32(2*(W - Z_C)); value = (64-k)*(1 + ln(1.01)*z_ref)
// with z_ref = fl(W2-|t|)/2, via contrib = wk * fma(ln(1.01)/2, z2, 1).
// Bin select: magic-number floor (no FRND/F2I/clamp), &63 wrap => reject path.
// wk = (MAGIC+64) - m  (exact: m = MAGIC + k integer).
// YUV: XLA unfused emission — separate FMUL/FADD, left-assoc, NO contraction.
// loss = (1/(B*H*W)) * sum_{pixels, 6ch(RGB+YUV)} [w(input) - w(reference)]

#define HW     65536
#define TPB    128
#define NBLK   512          // 65536 threads, 8 pixels each
#define MAGICF 12582912.0f  // 1.5 * 2^23
#define BIGW   12582976.0f  // MAGICF + 64
#define LNH    0.0049751654265840f   // ln(1.01)/2

__device__ double g_partial[NBLK];
__device__ unsigned int g_ticket = 0;

__device__ __forceinline__ void binw_acc(float x, const float* __restrict__ C2,
                                         float W2, float T2, float& acc) {
    float s  = __fadd_rn(x, 1.0f);                  // 2y exactly (y = s/2)
    float ef = fmaf(x, 29.090909090909f, 31.5f);    // selector - 0.5
    float m  = __fadd_rn(ef, MAGICF);               // int(m) = MAGIC + floor(sel)
    int   i  = __float_as_int(m) & 63;              // wrap => wrong center => reject
    float t  = __fsub_rn(s, C2[i]);                 // = 2*fl(y - c_k) bit-exact
    float at = fabsf(t);
    float wk = __fsub_rn(BIGW, m);                  // = 64 - k exactly
    float z2 = __fsub_rn(W2, at);                   // = 2*z_ref bit-exact
    float c  = __fmul_rn(wk, fmaf(LNH, z2, 1.0f));  // (64-k)*(1+ln1.01*z_ref)
    if (at < T2) acc = __fadd_rn(acc, c);           // predicated FADD
}

__device__ __forceinline__ float pix6(float r, float g, float b,
                                      const float* __restrict__ C2,
                                      float W2, float T2) {
    float acc = 0.0f;
    binw_acc(r, C2, W2, T2, acc);
    binw_acc(g, C2, W2, T2, acc);
    binw_acc(b, C2, W2, T2, acc);
    // Ordering (B): separate mul / add, left-assoc, every op rounded, NO fma.
    float yy = __fadd_rn(__fadd_rn(__fmul_rn(0.299f,    r), __fmul_rn(0.587f,    g)),
                         __fmul_rn(0.114f,    b));
    float uu = __fadd_rn(__fadd_rn(__fmul_rn(-0.14713f, r), __fmul_rn(-0.28886f, g)),
                         __fmul_rn(0.436f,    b));
    float vv = __fadd_rn(__fadd_rn(__fmul_rn(0.615f,    r), __fmul_rn(-0.51499f, g)),
                         __fmul_rn(-0.10001f, b));
    binw_acc(yy, C2, W2, T2, acc);
    binw_acc(uu, C2, W2, T2, acc);
    binw_acc(vv, C2, W2, T2, acc);
    return acc;
}

__global__ void __launch_bounds__(TPB, 4) hist_all(const float* __restrict__ A,
                                                   const float* __restrict__ R,
                                                   float* __restrict__ out,
                                                   double inv_n) {
    __shared__ float C2[64];
    __shared__ float sW2, sT2;
    __shared__ double sd[TPB];
    __shared__ bool amLast;

    // Exact f32 centers mirroring numpy linspace f64 rounding; 2x scaling exact.
    if (threadIdx.x < 64) {
        double start = -0.05;
        double step  = __ddiv_rn(__dsub_rn(1.05, start), 64.0);
        double e1    = __dadd_rn(__dmul_rn(1.0, step), start);
        double e2    = __dadd_rn(__dmul_rn(2.0, step), start);
        double delta = __dsub_rn(e2, e1);
        double half  = __dmul_rn(delta, 0.5);
        double ei    = __dadd_rn(__dmul_rn((double)threadIdx.x, step), start);
        float  c     = (float)__dadd_rn(ei, half);       // reference center f32
        C2[threadIdx.x] = 2.0f * c;                      // exact
        if (threadIdx.x == 0) {
            float W = (float)half;                       // reference W f32
            sW2 = 2.0f * W;                              // exact
            sT2 = (float)(2.0 * ((double)W - 5.990216e-6)); // 2(W - Z_C)
        }
    }
    __syncthreads();
    float W2 = sW2, T2 = sT2;

    // 8 pixels per thread: two float4 groups per channel per image.
    int gid = blockIdx.x * TPB + threadIdx.x;     // 0 .. 65535
    int b   = gid >> 13;                          // / (HW/8)
    int p8  = (gid & 8191) << 3;                  // 8 consecutive pixels
    size_t base = (size_t)b * (3 * HW) + p8;

    float4 ar0 = *(const float4*)(A + base);
    float4 ar1 = *(const float4*)(A + base + 4);
    float4 ag0 = *(const float4*)(A + base + HW);
    float4 ag1 = *(const float4*)(A + base + HW + 4);
    float4 ab0 = *(const float4*)(A + base + 2 * HW);
    float4 ab1 = *(const float4*)(A + base + 2 * HW + 4);
    float4 rr0 = *(const float4*)(R + base);
    float4 rr1 = *(const float4*)(R + base + 4);
    float4 rg0 = *(const float4*)(R + base + HW);
    float4 rg1 = *(const float4*)(R + base + HW + 4);
    float4 rb0 = *(const float4*)(R + base + 2 * HW);
    float4 rb1 = *(const float4*)(R + base + 2 * HW + 4);

    float acc;
    acc  = pix6(ar0.x, ag0.x, ab0.x, C2, W2, T2) - pix6(rr0.x, rg0.x, rb0.x, C2, W2, T2);
    acc += pix6(ar0.y, ag0.y, ab0.y, C2, W2, T2) - pix6(rr0.y, rg0.y, rb0.y, C2, W2, T2);
    acc += pix6(ar0.z, ag0.z, ab0.z, C2, W2, T2) - pix6(rr0.z, rg0.z, rb0.z, C2, W2, T2);
    acc += pix6(ar0.w, ag0.w, ab0.w, C2, W2, T2) - pix6(rr0.w, rg0.w, rb0.w, C2, W2, T2);
    acc += pix6(ar1.x, ag1.x, ab1.x, C2, W2, T2) - pix6(rr1.x, rg1.x, rb1.x, C2, W2, T2);
    acc += pix6(ar1.y, ag1.y, ab1.y, C2, W2, T2) - pix6(rr1.y, rg1.y, rb1.y, C2, W2, T2);
    acc += pix6(ar1.z, ag1.z, ab1.z, C2, W2, T2) - pix6(rr1.z, rg1.z, rb1.z, C2, W2, T2);
    acc += pix6(ar1.w, ag1.w, ab1.w, C2, W2, T2) - pix6(rr1.w, rg1.w, rb1.w, C2, W2, T2);

    sd[threadIdx.x] = (double)acc;
    __syncthreads();
    #pragma unroll
    for (int s = TPB / 2; s > 32; s >>= 1) {
        if (threadIdx.x < s) sd[threadIdx.x] += sd[threadIdx.x + s];
        __syncthreads();
    }
    if (threadIdx.x < 32) {
        double v = sd[threadIdx.x] + sd[threadIdx.x + 32];
        #pragma unroll
        for (int o = 16; o > 0; o >>= 1)
            v += __shfl_down_sync(0xffffffffu, v, o);
        if (threadIdx.x == 0) g_partial[blockIdx.x] = v;
    }

    // Last-block final reduction (deterministic fixed tree over partials).
    if (threadIdx.x == 0) {
        __threadfence();
        unsigned int t = atomicAdd(&g_ticket, 1u);
        amLast = (t == (unsigned int)(gridDim.x - 1));
    }
    __syncthreads();
    if (amLast) {
        __threadfence();
        double v = 0.0;
        #pragma unroll
        for (int i = 0; i < NBLK / TPB; i++)
            v += g_partial[threadIdx.x + i * TPB];
        sd[threadIdx.x] = v;
        __syncthreads();
        #pragma unroll
        for (int s = TPB / 2; s > 32; s >>= 1) {
            if (threadIdx.x < s) sd[threadIdx.x] += sd[threadIdx.x + s];
            __syncthreads();
        }
        if (threadIdx.x < 32) {
            double w2 = sd[threadIdx.x] + sd[threadIdx.x + 32];
            #pragma unroll
            for (int o = 16; o > 0; o >>= 1)
                w2 += __shfl_down_sync(0xffffffffu, w2, o);
            if (threadIdx.x == 0) {
                out[0] = (float)(w2 * inv_n);
                g_ticket = 0;           // reset for next graph replay
            }
        }
    }
}

extern "C" void kernel_launch(void* const* d_in, const int* in_sizes, int n_in,
                              void* d_out, int out_size) {
    const float* A = (const float*)d_in[0];   // input_img
    const float* R = (const float*)d_in[1];   // reference_img
    int total = in_sizes[0];                  // B*3*HW
    int npix  = total / 3;                    // B*HW
    hist_all<<<NBLK, TPB>>>(A, R, (float*)d_out, 1.0 / (double)npix);
}